// round 10
// baseline (speedup 1.0000x reference)
#include <cuda_runtime.h>
#include <cuda_bf16.h>
#include <cstdint>

#define B_    4
#define C_    64
#define T_    80
#define S_    2304
#define N_    128
#define NT_   10
#define TOUT_ 71
#define F_    320
#define KC    64
#define NCHUNK 36                 // chunks per tile
#define NTILE  160                // M128 tiles
#define GRID_G 148
#define NLONG  136                // CTAs with 39 chunks; rest 38
#define NTEN  96                  // tensor-path n columns
#define NSIMT 32                  // SIMT-path n columns

// ---------------- device scratch -------------------------------------------
__device__ __align__(16) __nv_bfloat16 g_wsT[N_*S_];    // [n][s] bf16 (tensor B)
__device__ __align__(16) float g_wsf[(S_/4)*NSIMT*4];   // [kq][nn][4k] fp32 (SIMT B)
__device__ float g_Rpart[NTILE*2*2*N_];                  // [tile][ord][fl][n]

// ---------------- helpers ---------------------------------------------------
__device__ __forceinline__ uint32_t smem_u32(const void* p) {
    uint32_t a;
    asm("{ .reg .u64 t; cvta.to.shared.u64 t, %1; cvt.u32.u64 %0, t; }" : "=r"(a) : "l"(p));
    return a;
}
__device__ __forceinline__ uint32_t pack_bf16(float lo, float hi) {
    uint32_t r;
    asm("cvt.rn.bf16x2.f32 %0, %1, %2;" : "=r"(r) : "f"(hi), "f"(lo));
    return r;
}
__device__ __forceinline__ void cp16(uint32_t dst, const void* src) {
    asm volatile("cp.async.cg.shared.global [%0], [%1], 16;" :: "r"(dst), "l"(src) : "memory");
}
#define CP_COMMIT() asm volatile("cp.async.commit_group;" ::: "memory")
#define CP_WAIT1()  asm volatile("cp.async.wait_group 1;" ::: "memory")

__device__ __forceinline__ void mma_bf16(float* d, const uint32_t* a, const uint32_t* b) {
    asm volatile("mma.sync.aligned.m16n8k16.row.col.f32.bf16.bf16.f32 "
        "{%0,%1,%2,%3}, {%4,%5,%6,%7}, {%8,%9}, {%0,%1,%2,%3};"
        : "+f"(d[0]), "+f"(d[1]), "+f"(d[2]), "+f"(d[3])
        : "r"(a[0]), "r"(a[1]), "r"(a[2]), "r"(a[3]), "r"(b[0]), "r"(b[1]));
}
// packed fp32 FMA (Blackwell FFMA2): two independent fp32 FMAs per instruction
__device__ __forceinline__ void fma_x2(unsigned long long& acc,
                                       unsigned long long a, unsigned long long b) {
    asm("fma.rn.f32x2 %0, %1, %2, %0;" : "+l"(acc) : "l"(a), "l"(b));
}

// A: fp32 tile 128 rows x 256B, 32B granules g=0..7, XOR swizzle (R3/R6-proven)
__device__ __forceinline__ uint32_t aswz(int r, int g) {
    return (uint32_t)(r * 256 + (((g ^ (r & 7)) & 7) << 5));
}
// B: bf16 tile 128 rows x 128B, 16B granules (R3/R6-proven)
__device__ __forceinline__ uint32_t bswz(int n, int g) {
    return (uint32_t)(n * 128 + (((g ^ (n & 7)) & 7) << 4));
}

// ---------------------------------------------------------------------------
// 1) prep: blocks 0..127 -> wsT row n (bf16); n>=96 also fp32 transposed slice;
//    blocks 128..159 zero Rpart
// ---------------------------------------------------------------------------
__global__ void prep_kernel(const float* __restrict__ wx, const float* __restrict__ wy,
                            const float* __restrict__ wsx, const float* __restrict__ wsy) {
    int blk = blockIdx.x, tid = threadIdx.x;
    if (blk < 128) {
        int n = blk;
        __shared__ float gx[64], gy[36], invz;
        if (tid < 64) {
            float rx = fmaxf(wsx[n], 0.0f);
            float inv2sx = 1.0f / (2.0f * (0.1f + rx * rx));
            float xv = ((float)tid - 32.0f + 0.5f) / 64.0f;
            float d = xv - wx[n];
            gx[tid] = expf(-d * d * inv2sx);
        } else if (tid < 100) {
            int yp = tid - 64;
            float ry = fmaxf(wsy[n], 0.0f);
            float inv2sy = 1.0f / (2.0f * (0.1f + ry * ry));
            float yv = ((float)yp - 18.0f + 0.5f) / 36.0f;
            float d = yv - wy[n];
            gy[yp] = expf(-d * d * inv2sy);
        }
        __syncthreads();
        if (tid == 0) {
            float sgx = 0.0f, sgy = 0.0f;
            for (int i = 0; i < 64; i++) sgx += gx[i];
            for (int i = 0; i < 36; i++) sgy += gy[i];
            invz = 1.0f / (0.1f + sgx * sgy);
        }
        __syncthreads();
        float iz = invz;
        for (int s = tid; s < S_; s += 256) {
            float v = gy[s >> 6] * gx[s & 63] * iz;
            g_wsT[(size_t)n * S_ + s] = __float2bfloat16(v);
            if (n >= NTEN)
                g_wsf[(size_t)(s >> 2) * (NSIMT * 4) + (n - NTEN) * 4 + (s & 3)] = v;
        }
    } else {
        int base = (blk - 128) * 2560;
        for (int q = tid; q < 2560; q += 256) g_Rpart[base + q] = 0.0f;
    }
}

// ---------------------------------------------------------------------------
// 2) GEMM: grid 148, static chunk ranges. 384 threads:
//    warps 0-7  : bf16 mma.sync on n[0,96)  (tensor pipe)
//    warps 8-11 : fp32 fma.rn.f32x2 on n[96,128)  (fma pipe)
// ---------------------------------------------------------------------------
#define SM_A0   0
#define SM_A1   32768
#define SM_B0   65536
#define SM_B1   81920
#define SM_BS0  98304
#define SM_BS1  106496
#define SM_T1   114688
#define T1_STRIDE 132
#define SMEM_SZ (114688 + 128*T1_STRIDE*4)   // 182272

extern "C" __global__ void __launch_bounds__(384, 1)
gemm_kernel(const float* __restrict__ x, const float* __restrict__ wc) {
    extern __shared__ __align__(16) char smem[];
    const uint32_t sb = smem_u32(smem);
    const int tid  = threadIdx.x;
    const int wid  = tid >> 5;
    const int lane = tid & 31;
    // tensor-warp mapping
    const int wm   = wid & 3;
    const int wn   = wid >> 2;      // 0..1 for wid<8
    const int lrow = lane >> 2;
    const int lq   = lane & 3;
    const int lr   = tid >> 1;      // A loader row (tid<256)
    const int lh   = tid & 1;
    // SIMT-warp mapping (tid>=256)
    const int st   = tid - 256;     // 0..127
    const int sw   = st >> 5;       // 0..3, rows sw*32..+31
    const int srg  = lane >> 2;     // 8 row-groups x 4 rows
    const int sng  = lane & 3;      // 4 n-groups x 8 cols
    const int sr0  = sw * 32 + srg * 4;
    const int snn0 = sng * 8;       // local n offset in [0,32)

    const int bi = blockIdx.x;
    const int s  = (bi < NLONG) ? 39 * bi : 39 * NLONG + 38 * (bi - NLONG);
    const int e  = s + ((bi < NLONG) ? 39 : 38);

    const uint32_t abuf[2]  = { sb + SM_A0,  sb + SM_A1 };
    const uint32_t bbuf[2]  = { sb + SM_B0,  sb + SM_B1 };
    const uint32_t bsbuf[2] = { sb + SM_BS0, sb + SM_BS1 };

    auto issue = [&](int g, int p) {
        int m = g / NCHUNK;
        int k = g - m * NCHUNK;
        if (tid < 256) {
            int gr = m * 128 + lr;
            int f  = gr >> 6;
            int c  = gr & 63;
            int bb = f / T_;
            int tt = f - bb * T_;
            const float* as = x + ((size_t)((bb * C_ + c) * T_ + tt)) * S_ + k * KC + lh * 32;
#pragma unroll
            for (int jj = 0; jj < 4; jj++) {
                uint32_t d = abuf[p] + aswz(lr, lh * 4 + jj);
                cp16(d,      as + jj * 8);
                cp16(d + 16, as + jj * 8 + 4);
            }
            const __nv_bfloat16* bs = g_wsT + (size_t)lr * S_ + k * KC + lh * 32;
#pragma unroll
            for (int jj = 0; jj < 4; jj++)
                cp16(bbuf[p] + bswz(lr, lh * 4 + jj), bs + jj * 8);
        } else {
            // SIMT B slice: 512 x 16B granules, transposed [kq][nn][4k] layout
            const float* src = g_wsf + (size_t)(k * 16) * (NSIMT * 4);
#pragma unroll
            for (int jj = 0; jj < 4; jj++) {
                int gi = st * 4 + jj;
                cp16(bsbuf[p] + gi * 16, src + gi * 4);
            }
        }
    };

    // tensor accumulators (warps 0-7): n width 48/warp -> 6 j-tiles
    float acc[2][6][4];
#pragma unroll
    for (int mt = 0; mt < 2; mt++)
#pragma unroll
        for (int j = 0; j < 6; j++)
#pragma unroll
            for (int q = 0; q < 4; q++) acc[mt][j][q] = 0.0f;
    // SIMT accumulators (warps 8-11): 4r x 8n x (k-pair) packed
    unsigned long long acc2[4][8];
#pragma unroll
    for (int i = 0; i < 4; i++)
#pragma unroll
        for (int j = 0; j < 8; j++) acc2[i][j] = 0ULL;

    issue(s, 0);     CP_COMMIT();
    issue(s + 1, 1); CP_COMMIT();

    float* Tsm = (float*)(smem + SM_T1);

    for (int g = s; g < e; g++) {
        const int p = (g - s) & 1;
        CP_WAIT1();
        __syncthreads();

        const uint32_t Ab = abuf[p];
        if (tid < 256) {
            const uint32_t Bb = bbuf[p];
#pragma unroll
            for (int q = 0; q < 4; q++) {
                uint32_t afr[2][4];
#pragma unroll
                for (int mt = 0; mt < 2; mt++) {
#pragma unroll
                    for (int half = 0; half < 2; half++) {
#pragma unroll
                        for (int dr = 0; dr < 2; dr++) {
                            float2 v;
                            uint32_t ad = Ab + aswz(wm * 32 + mt * 16 + lrow + dr * 8,
                                                    q * 2 + half) + lq * 8;
                            asm volatile("ld.shared.v2.f32 {%0,%1}, [%2];"
                                         : "=f"(v.x), "=f"(v.y) : "r"(ad));
                            afr[mt][half * 2 + dr] = pack_bf16(v.x, v.y);
                        }
                    }
                }
                uint32_t bfr[6][2];
#pragma unroll
                for (int j = 0; j < 6; j++) {
                    int n = wn * 48 + j * 8 + lrow;
#pragma unroll
                    for (int half = 0; half < 2; half++) {
                        asm volatile("ld.shared.b32 %0, [%1];"
                            : "=r"(bfr[j][half]) : "r"(Bb + bswz(n, q * 2 + half) + lq * 4));
                    }
                }
#pragma unroll
                for (int mt = 0; mt < 2; mt++)
#pragma unroll
                    for (int j = 0; j < 6; j++)
                        mma_bf16(acc[mt][j], afr[mt], bfr[j]);
            }
        } else {
            const uint32_t Bs = bsbuf[p];
#pragma unroll
            for (int q4 = 0; q4 < 16; q4++) {
                unsigned long long a2[4][2];
#pragma unroll
                for (int i = 0; i < 4; i++) {
                    uint32_t ad = Ab + aswz(sr0 + i, q4 >> 1) + (q4 & 1) * 16;
                    asm volatile("ld.shared.v2.u64 {%0,%1}, [%2];"
                                 : "=l"(a2[i][0]), "=l"(a2[i][1]) : "r"(ad));
                }
                unsigned long long b2[8][2];
#pragma unroll
                for (int j = 0; j < 8; j++) {
                    uint32_t bd = Bs + (uint32_t)((q4 * 32 + snn0 + j) * 16);
                    asm volatile("ld.shared.v2.u64 {%0,%1}, [%2];"
                                 : "=l"(b2[j][0]), "=l"(b2[j][1]) : "r"(bd));
                }
#pragma unroll
                for (int i = 0; i < 4; i++)
#pragma unroll
                    for (int j = 0; j < 8; j++) {
                        fma_x2(acc2[i][j], a2[i][0], b2[j][0]);
                        fma_x2(acc2[i][j], a2[i][1], b2[j][1]);
                    }
            }
        }
        __syncthreads();
        if (g + 2 < e) issue(g + 2, p);
        CP_COMMIT();

        // ---- tile boundary or range end: flush partial R ----
        if ((g + 1 == e) || ((g + 1) % NCHUNK == 0)) {
            int m = g / NCHUNK;
            __syncthreads();
            if (tid < 256) {
#pragma unroll
                for (int mt = 0; mt < 2; mt++) {
#pragma unroll
                    for (int j = 0; j < 6; j++) {
                        int r0  = wm * 32 + mt * 16 + lrow;
                        int col = wn * 48 + j * 8 + lq * 2;
                        uint32_t a0 = sb + SM_T1 + (uint32_t)((r0 * T1_STRIDE + col) * 4);
                        uint32_t a1 = sb + SM_T1 + (uint32_t)(((r0 + 8) * T1_STRIDE + col) * 4);
                        asm volatile("st.shared.v2.f32 [%0], {%1,%2};"
                                     :: "r"(a0), "f"(acc[mt][j][0]), "f"(acc[mt][j][1]));
                        asm volatile("st.shared.v2.f32 [%0], {%1,%2};"
                                     :: "r"(a1), "f"(acc[mt][j][2]), "f"(acc[mt][j][3]));
                    }
                }
#pragma unroll
                for (int mt = 0; mt < 2; mt++)
#pragma unroll
                    for (int j = 0; j < 6; j++)
#pragma unroll
                        for (int q = 0; q < 4; q++) acc[mt][j][q] = 0.0f;
            } else {
#pragma unroll
                for (int i = 0; i < 4; i++) {
#pragma unroll
                    for (int j = 0; j < 8; j++) {
                        float lo = __uint_as_float((uint32_t)(acc2[i][j] & 0xFFFFFFFFULL));
                        float hi = __uint_as_float((uint32_t)(acc2[i][j] >> 32));
                        Tsm[(sr0 + i) * T1_STRIDE + NTEN + snn0 + j] = lo + hi;
                        acc2[i][j] = 0ULL;
                    }
                }
            }
            __syncthreads();
            if (tid < 256) {
                int fl = tid >> 7;
                int n  = tid & 127;
                float sum = 0.0f;
#pragma unroll 16
                for (int c2 = 0; c2 < 64; c2++)
                    sum += Tsm[(fl * 64 + c2) * T1_STRIDE + n] * __ldg(&wc[c2 * N_ + n]);
                int ord = (s > m * NCHUNK) ? 1 : 0;
                g_Rpart[m * 512 + ord * 256 + fl * 128 + n] = sum;
            }
        }
    }
}

// ---------------------------------------------------------------------------
// 3) temporal conv: one warp per (b, n) row
// ---------------------------------------------------------------------------
__global__ void conv_kernel(const float* __restrict__ wt, const float* __restrict__ wb,
                            float* __restrict__ out) {
    __shared__ float rr[8][80];
    __shared__ float wts[8][10];
    int wid = threadIdx.x >> 5, lane = threadIdx.x & 31;
    int row = blockIdx.x * 8 + wid;        // row = b*N + n
    int b = row >> 7, n = row & 127;
    if (lane < 10) wts[wid][lane] = wt[lane * N_ + n];
#pragma unroll
    for (int t0 = lane; t0 < T_; t0 += 32) {
        int f = b * T_ + t0;
        int m = f >> 1, fl = f & 1;
        rr[wid][t0] = g_Rpart[m * 512 + fl * 128 + n]
                    + g_Rpart[m * 512 + 256 + fl * 128 + n];
    }
    __syncwarp();
    float bias = wb[n];
    for (int t0 = lane; t0 < TOUT_; t0 += 32) {
        float sum = bias;
#pragma unroll
        for (int k = 0; k < NT_; k++) sum += rr[wid][t0 + k] * wts[wid][k];
        out[(size_t)row * TOUT_ + t0] = sum;
    }
}

// ---------------------------------------------------------------------------
extern "C" void kernel_launch(void* const* d_in, const int* in_sizes, int n_in,
                              void* d_out, int out_size) {
    (void)in_sizes; (void)n_in; (void)out_size;
    const float* x   = (const float*)d_in[0];
    const float* wc  = (const float*)d_in[2];
    const float* wx  = (const float*)d_in[3];
    const float* wy  = (const float*)d_in[4];
    const float* wsx = (const float*)d_in[5];
    const float* wsy = (const float*)d_in[6];
    const float* wt  = (const float*)d_in[7];
    const float* wb  = (const float*)d_in[8];
    float* out = (float*)d_out;

    cudaFuncSetAttribute(gemm_kernel, cudaFuncAttributeMaxDynamicSharedMemorySize, SMEM_SZ);

    prep_kernel<<<160, 256>>>(wx, wy, wsx, wsy);
    gemm_kernel<<<GRID_G, 384, SMEM_SZ>>>(x, wc);
    conv_kernel<<<(B_ * N_) / 8, 256>>>(wt, wb, out);
}

// round 11
// speedup vs baseline: 4.1184x; 4.1184x over previous
#include <cuda_runtime.h>
#include <cuda_bf16.h>
#include <cstdint>

#define B_    4
#define C_    64
#define T_    80
#define S_    2304
#define N_    128
#define NT_   10
#define TOUT_ 71
#define F_    320
#define KC    64
#define NCHUNK 36                 // chunks per tile
#define NTILE  160                // M128 tiles
#define GRID_G 148
#define NLONG  136                // CTAs with 39 chunks; rest 38

// ---------------- device scratch -------------------------------------------
__device__ __align__(16) __nv_bfloat16 g_wsT[N_*S_];    // [n][s] bf16
__device__ float g_Rpart[NTILE*2*2*N_];                  // [tile][ord][fl][n]

// ---------------- helpers ---------------------------------------------------
__device__ __forceinline__ uint32_t smem_u32(const void* p) {
    uint32_t a;
    asm("{ .reg .u64 t; cvta.to.shared.u64 t, %1; cvt.u32.u64 %0, t; }" : "=r"(a) : "l"(p));
    return a;
}
__device__ __forceinline__ uint32_t pack_bf16(float lo, float hi) {
    uint32_t r;
    asm("cvt.rn.bf16x2.f32 %0, %1, %2;" : "=r"(r) : "f"(hi), "f"(lo));
    return r;
}
__device__ __forceinline__ void cp16(uint32_t dst, const void* src) {
    asm volatile("cp.async.cg.shared.global [%0], [%1], 16;" :: "r"(dst), "l"(src) : "memory");
}
#define CP_COMMIT() asm volatile("cp.async.commit_group;" ::: "memory")
#define CP_WAIT1()  asm volatile("cp.async.wait_group 1;" ::: "memory")

__device__ __forceinline__ void mma_bf16(float* d, const uint32_t* a, const uint32_t* b) {
    asm volatile("mma.sync.aligned.m16n8k16.row.col.f32.bf16.bf16.f32 "
        "{%0,%1,%2,%3}, {%4,%5,%6,%7}, {%8,%9}, {%0,%1,%2,%3};"
        : "+f"(d[0]), "+f"(d[1]), "+f"(d[2]), "+f"(d[3])
        : "r"(a[0]), "r"(a[1]), "r"(a[2]), "r"(a[3]), "r"(b[0]), "r"(b[1]));
}

// A: fp32 tile 128 rows x 256B, 32B granules g=0..7, XOR swizzle (R3/R6-proven)
__device__ __forceinline__ uint32_t aswz(int r, int g) {
    return (uint32_t)(r * 256 + (((g ^ (r & 7)) & 7) << 5));
}
// B: bf16 tile 128 rows x 128B, 16B granules (R3/R6-proven)
__device__ __forceinline__ uint32_t bswz(int n, int g) {
    return (uint32_t)(n * 128 + (((g ^ (n & 7)) & 7) << 4));
}

// ---------------------------------------------------------------------------
// 1) prep: blocks 0..127 -> wsT row n; blocks 128..159 zero Rpart  (R6-proven)
// ---------------------------------------------------------------------------
__global__ void prep_kernel(const float* __restrict__ wx, const float* __restrict__ wy,
                            const float* __restrict__ wsx, const float* __restrict__ wsy) {
    int blk = blockIdx.x, tid = threadIdx.x;
    if (blk < 128) {
        int n = blk;
        __shared__ float gx[64], gy[36], invz;
        if (tid < 64) {
            float rx = fmaxf(wsx[n], 0.0f);
            float inv2sx = 1.0f / (2.0f * (0.1f + rx * rx));
            float xv = ((float)tid - 32.0f + 0.5f) / 64.0f;
            float d = xv - wx[n];
            gx[tid] = expf(-d * d * inv2sx);
        } else if (tid < 100) {
            int yp = tid - 64;
            float ry = fmaxf(wsy[n], 0.0f);
            float inv2sy = 1.0f / (2.0f * (0.1f + ry * ry));
            float yv = ((float)yp - 18.0f + 0.5f) / 36.0f;
            float d = yv - wy[n];
            gy[yp] = expf(-d * d * inv2sy);
        }
        __syncthreads();
        if (tid == 0) {
            float sgx = 0.0f, sgy = 0.0f;
            for (int i = 0; i < 64; i++) sgx += gx[i];
            for (int i = 0; i < 36; i++) sgy += gy[i];
            invz = 1.0f / (0.1f + sgx * sgy);
        }
        __syncthreads();
        float iz = invz;
        for (int s = tid; s < S_; s += 256)
            g_wsT[(size_t)n * S_ + s] = __float2bfloat16(gy[s >> 6] * gx[s & 63] * iz);
    } else {
        int base = (blk - 128) * 2560;
        for (int q = tid; q < 2560; q += 256) g_Rpart[base + q] = 0.0f;
    }
}

// ---------------------------------------------------------------------------
// 2) GEMM: grid 148, 512 threads (16 warps, 4/SMSP), static chunk ranges.
//    Identical datapath to R6; each warp owns n=32 (4 j-tiles).
// ---------------------------------------------------------------------------
#define SM_A0   0
#define SM_A1   32768
#define SM_B0   65536
#define SM_B1   81920
#define SM_T1   98304
#define T1_STRIDE 132
#define SMEM_SZ (98304 + 128*T1_STRIDE*4)   // 165888

extern "C" __global__ void __launch_bounds__(512, 1)
gemm_kernel(const float* __restrict__ x, const float* __restrict__ wc) {
    extern __shared__ __align__(16) char smem[];
    const uint32_t sb = smem_u32(smem);
    const int tid  = threadIdx.x;
    const int wid  = tid >> 5;
    const int lane = tid & 31;
    const int wm   = wid & 3;       // m block: rows wm*32..+31
    const int wn   = wid >> 2;      // n block: cols wn*32..+31
    const int lrow = lane >> 2;
    const int lq   = lane & 3;
    const int lr   = tid >> 2;      // loader row 0..127
    const int lz   = tid & 3;       // loader quarter

    const int bi = blockIdx.x;
    const int s  = (bi < NLONG) ? 39 * bi : 39 * NLONG + 38 * (bi - NLONG);
    const int e  = s + ((bi < NLONG) ? 39 : 38);

    const uint32_t abuf[2] = { sb + SM_A0, sb + SM_A1 };
    const uint32_t bbuf[2] = { sb + SM_B0, sb + SM_B1 };

    auto issue = [&](int g, int p) {
        int m = g / NCHUNK;
        int k = g - m * NCHUNK;
        int gr = m * 128 + lr;
        int f  = gr >> 6;
        int c  = gr & 63;
        int bb = f / T_;
        int tt = f - bb * T_;
        const float* xrow = x + ((size_t)((bb * C_ + c) * T_ + tt)) * S_ + k * KC;
#pragma unroll
        for (int jj = 0; jj < 2; jj++) {
            int gA = lz * 2 + jj;                 // 32B granule
            uint32_t d = abuf[p] + aswz(lr, gA);
            cp16(d,      xrow + gA * 8);
            cp16(d + 16, xrow + gA * 8 + 4);
        }
        const __nv_bfloat16* bs = g_wsT + (size_t)lr * S_ + k * KC;
#pragma unroll
        for (int jj = 0; jj < 2; jj++) {
            int gB = lz * 2 + jj;                 // 16B granule
            cp16(bbuf[p] + bswz(lr, gB), bs + gB * 8);
        }
    };

    float acc[2][4][4];
#pragma unroll
    for (int mt = 0; mt < 2; mt++)
#pragma unroll
        for (int j = 0; j < 4; j++)
#pragma unroll
            for (int q = 0; q < 4; q++) acc[mt][j][q] = 0.0f;

    issue(s, 0);     CP_COMMIT();
    issue(s + 1, 1); CP_COMMIT();

    float* Tsm = (float*)(smem + SM_T1);

    for (int g = s; g < e; g++) {
        const int p = (g - s) & 1;
        CP_WAIT1();
        __syncthreads();

        const uint32_t Ab = abuf[p], Bb = bbuf[p];
#pragma unroll
        for (int q = 0; q < 4; q++) {
            uint32_t afr[2][4];
#pragma unroll
            for (int mt = 0; mt < 2; mt++) {
#pragma unroll
                for (int half = 0; half < 2; half++) {
#pragma unroll
                    for (int dr = 0; dr < 2; dr++) {
                        float2 v;
                        uint32_t ad = Ab + aswz(wm * 32 + mt * 16 + lrow + dr * 8,
                                                q * 2 + half) + lq * 8;
                        asm volatile("ld.shared.v2.f32 {%0,%1}, [%2];"
                                     : "=f"(v.x), "=f"(v.y) : "r"(ad));
                        afr[mt][half * 2 + dr] = pack_bf16(v.x, v.y);
                    }
                }
            }
            uint32_t bfr[4][2];
#pragma unroll
            for (int j = 0; j < 4; j++) {
                int n = wn * 32 + j * 8 + lrow;
#pragma unroll
                for (int half = 0; half < 2; half++) {
                    asm volatile("ld.shared.b32 %0, [%1];"
                        : "=r"(bfr[j][half]) : "r"(Bb + bswz(n, q * 2 + half) + lq * 4));
                }
            }
#pragma unroll
            for (int mt = 0; mt < 2; mt++)
#pragma unroll
                for (int j = 0; j < 4; j++)
                    mma_bf16(acc[mt][j], afr[mt], bfr[j]);
        }
        __syncthreads();
        if (g + 2 < e) issue(g + 2, p);
        CP_COMMIT();

        // ---- tile boundary or range end: flush partial R ----
        if ((g + 1 == e) || ((g + 1) % NCHUNK == 0)) {
            int m = g / NCHUNK;
            __syncthreads();
#pragma unroll
            for (int mt = 0; mt < 2; mt++) {
#pragma unroll
                for (int j = 0; j < 4; j++) {
                    int r0  = wm * 32 + mt * 16 + lrow;
                    int col = wn * 32 + j * 8 + lq * 2;
                    uint32_t a0 = sb + SM_T1 + (uint32_t)((r0 * T1_STRIDE + col) * 4);
                    uint32_t a1 = sb + SM_T1 + (uint32_t)(((r0 + 8) * T1_STRIDE + col) * 4);
                    asm volatile("st.shared.v2.f32 [%0], {%1,%2};"
                                 :: "r"(a0), "f"(acc[mt][j][0]), "f"(acc[mt][j][1]));
                    asm volatile("st.shared.v2.f32 [%0], {%1,%2};"
                                 :: "r"(a1), "f"(acc[mt][j][2]), "f"(acc[mt][j][3]));
                }
            }
            __syncthreads();
            if (tid < 256) {
                int fl = tid >> 7;
                int n  = tid & 127;
                float sum = 0.0f;
#pragma unroll 16
                for (int c2 = 0; c2 < 64; c2++)
                    sum += Tsm[(fl * 64 + c2) * T1_STRIDE + n] * __ldg(&wc[c2 * N_ + n]);
                int ord = (s > m * NCHUNK) ? 1 : 0;
                g_Rpart[m * 512 + ord * 256 + fl * 128 + n] = sum;
            }
#pragma unroll
            for (int mt = 0; mt < 2; mt++)
#pragma unroll
                for (int j = 0; j < 4; j++)
#pragma unroll
                    for (int q = 0; q < 4; q++) acc[mt][j][q] = 0.0f;
        }
    }
}

// ---------------------------------------------------------------------------
// 3) temporal conv: one warp per (b, n) row
// ---------------------------------------------------------------------------
__global__ void conv_kernel(const float* __restrict__ wt, const float* __restrict__ wb,
                            float* __restrict__ out) {
    __shared__ float rr[8][80];
    __shared__ float wts[8][10];
    int wid = threadIdx.x >> 5, lane = threadIdx.x & 31;
    int row = blockIdx.x * 8 + wid;        // row = b*N + n
    int b = row >> 7, n = row & 127;
    if (lane < 10) wts[wid][lane] = wt[lane * N_ + n];
#pragma unroll
    for (int t0 = lane; t0 < T_; t0 += 32) {
        int f = b * T_ + t0;
        int m = f >> 1, fl = f & 1;
        rr[wid][t0] = g_Rpart[m * 512 + fl * 128 + n]
                    + g_Rpart[m * 512 + 256 + fl * 128 + n];
    }
    __syncwarp();
    float bias = wb[n];
    for (int t0 = lane; t0 < TOUT_; t0 += 32) {
        float sum = bias;
#pragma unroll
        for (int k = 0; k < NT_; k++) sum += rr[wid][t0 + k] * wts[wid][k];
        out[(size_t)row * TOUT_ + t0] = sum;
    }
}

// ---------------------------------------------------------------------------
extern "C" void kernel_launch(void* const* d_in, const int* in_sizes, int n_in,
                              void* d_out, int out_size) {
    (void)in_sizes; (void)n_in; (void)out_size;
    const float* x   = (const float*)d_in[0];
    const float* wc  = (const float*)d_in[2];
    const float* wx  = (const float*)d_in[3];
    const float* wy  = (const float*)d_in[4];
    const float* wsx = (const float*)d_in[5];
    const float* wsy = (const float*)d_in[6];
    const float* wt  = (const float*)d_in[7];
    const float* wb  = (const float*)d_in[8];
    float* out = (float*)d_out;

    cudaFuncSetAttribute(gemm_kernel, cudaFuncAttributeMaxDynamicSharedMemorySize, SMEM_SZ);

    prep_kernel<<<160, 256>>>(wx, wy, wsx, wsy);
    gemm_kernel<<<GRID_G, 512, SMEM_SZ>>>(x, wc);
    conv_kernel<<<(B_ * N_) / 8, 256>>>(wt, wb, out);
}

// round 12
// speedup vs baseline: 4.4621x; 1.0834x over previous
#include <cuda_runtime.h>
#include <cuda_bf16.h>
#include <cstdint>

#define B_    4
#define C_    64
#define T_    80
#define S_    2304
#define N_    128
#define NT_   10
#define TOUT_ 71
#define F_    320
#define KC    64
#define NCHUNK 36                 // chunks per tile
#define NTILE  160                // M128 tiles
#define GRID_G 148
#define NLONG  136                // CTAs with 39 chunks; rest 38

// ---------------- device scratch -------------------------------------------
__device__ __align__(16) __nv_bfloat16 g_wsT[N_*S_];    // [n][s] bf16
__device__ float g_Rpart[NTILE*2*2*N_];                  // [tile][ord][fl][n]

// ---------------- helpers ---------------------------------------------------
__device__ __forceinline__ uint32_t smem_u32(const void* p) {
    uint32_t a;
    asm("{ .reg .u64 t; cvta.to.shared.u64 t, %1; cvt.u32.u64 %0, t; }" : "=r"(a) : "l"(p));
    return a;
}
__device__ __forceinline__ uint32_t pack_bf16(float lo, float hi) {
    uint32_t r;
    asm("cvt.rn.bf16x2.f32 %0, %1, %2;" : "=r"(r) : "f"(hi), "f"(lo));
    return r;
}
__device__ __forceinline__ void cp16(uint32_t dst, const void* src) {
    asm volatile("cp.async.cg.shared.global [%0], [%1], 16;" :: "r"(dst), "l"(src) : "memory");
}
#define CP_COMMIT() asm volatile("cp.async.commit_group;" ::: "memory")
#define CP_WAIT1()  asm volatile("cp.async.wait_group 1;" ::: "memory")

__device__ __forceinline__ void mma_bf16(float* d, const uint32_t* a, const uint32_t* b) {
    asm volatile("mma.sync.aligned.m16n8k16.row.col.f32.bf16.bf16.f32 "
        "{%0,%1,%2,%3}, {%4,%5,%6,%7}, {%8,%9}, {%0,%1,%2,%3};"
        : "+f"(d[0]), "+f"(d[1]), "+f"(d[2]), "+f"(d[3])
        : "r"(a[0]), "r"(a[1]), "r"(a[2]), "r"(a[3]), "r"(b[0]), "r"(b[1]));
}

// A: fp32 tile 128 rows x 256B, 32B granules g=0..7, XOR swizzle (R3/R6-proven)
__device__ __forceinline__ uint32_t aswz(int r, int g) {
    return (uint32_t)(r * 256 + (((g ^ (r & 7)) & 7) << 5));
}
// B: bf16 tile 128 rows x 128B, 16B granules (R3/R6-proven)
__device__ __forceinline__ uint32_t bswz(int n, int g) {
    return (uint32_t)(n * 128 + (((g ^ (n & 7)) & 7) << 4));
}

// ---------------------------------------------------------------------------
// 1) prep: blocks 0..127 -> wsT row n; blocks 128..159 zero Rpart  (R6-proven)
// ---------------------------------------------------------------------------
__global__ void prep_kernel(const float* __restrict__ wx, const float* __restrict__ wy,
                            const float* __restrict__ wsx, const float* __restrict__ wsy) {
    int blk = blockIdx.x, tid = threadIdx.x;
    if (blk < 128) {
        int n = blk;
        __shared__ float gx[64], gy[36], invz;
        if (tid < 64) {
            float rx = fmaxf(wsx[n], 0.0f);
            float inv2sx = 1.0f / (2.0f * (0.1f + rx * rx));
            float xv = ((float)tid - 32.0f + 0.5f) / 64.0f;
            float d = xv - wx[n];
            gx[tid] = expf(-d * d * inv2sx);
        } else if (tid < 100) {
            int yp = tid - 64;
            float ry = fmaxf(wsy[n], 0.0f);
            float inv2sy = 1.0f / (2.0f * (0.1f + ry * ry));
            float yv = ((float)yp - 18.0f + 0.5f) / 36.0f;
            float d = yv - wy[n];
            gy[yp] = expf(-d * d * inv2sy);
        }
        __syncthreads();
        if (tid == 0) {
            float sgx = 0.0f, sgy = 0.0f;
            for (int i = 0; i < 64; i++) sgx += gx[i];
            for (int i = 0; i < 36; i++) sgy += gy[i];
            invz = 1.0f / (0.1f + sgx * sgy);
        }
        __syncthreads();
        float iz = invz;
        for (int s = tid; s < S_; s += 256)
            g_wsT[(size_t)n * S_ + s] = __float2bfloat16(gy[s >> 6] * gx[s & 63] * iz);
    } else {
        int base = (blk - 128) * 2560;
        for (int q = tid; q < 2560; q += 256) g_Rpart[base + q] = 0.0f;
    }
}

// ---------------------------------------------------------------------------
// 2) GEMM: grid 148, 512 threads, 3-stage cp.async, ONE barrier per chunk.
// ---------------------------------------------------------------------------
#define SM_A    0          // 3 x 32768
#define SM_B    98304      // 3 x 16384
#define SM_T1   147456
#define T1_STRIDE 132
#define SMEM_SZ (147456 + 128*T1_STRIDE*4)   // 215040

extern "C" __global__ void __launch_bounds__(512, 1)
gemm_kernel(const float* __restrict__ x, const float* __restrict__ wc) {
    extern __shared__ __align__(16) char smem[];
    const uint32_t sb = smem_u32(smem);
    const int tid  = threadIdx.x;
    const int wid  = tid >> 5;
    const int lane = tid & 31;
    const int wm   = wid & 3;       // m block: rows wm*32..+31
    const int wn   = wid >> 2;      // n block: cols wn*32..+31
    const int lrow = lane >> 2;
    const int lq   = lane & 3;
    const int lr   = tid >> 2;      // loader row 0..127
    const int lz   = tid & 3;       // loader quarter

    const int bi = blockIdx.x;
    const int s  = (bi < NLONG) ? 39 * bi : 39 * NLONG + 38 * (bi - NLONG);
    const int e  = s + ((bi < NLONG) ? 39 : 38);

    auto issue = [&](int g, int p) {
        int m = g / NCHUNK;
        int k = g - m * NCHUNK;
        int gr = m * 128 + lr;
        int f  = gr >> 6;
        int c  = gr & 63;
        int bb = f / T_;
        int tt = f - bb * T_;
        const float* xrow = x + ((size_t)((bb * C_ + c) * T_ + tt)) * S_ + k * KC;
        uint32_t ab = sb + SM_A + (uint32_t)p * 32768u;
        uint32_t bb2 = sb + SM_B + (uint32_t)p * 16384u;
#pragma unroll
        for (int jj = 0; jj < 2; jj++) {
            int gA = lz * 2 + jj;                 // 32B granule
            uint32_t d = ab + aswz(lr, gA);
            cp16(d,      xrow + gA * 8);
            cp16(d + 16, xrow + gA * 8 + 4);
        }
        const __nv_bfloat16* bs = g_wsT + (size_t)lr * S_ + k * KC;
#pragma unroll
        for (int jj = 0; jj < 2; jj++) {
            int gB = lz * 2 + jj;                 // 16B granule
            cp16(bb2 + bswz(lr, gB), bs + gB * 8);
        }
    };

    float acc[2][4][4];
#pragma unroll
    for (int mt = 0; mt < 2; mt++)
#pragma unroll
        for (int j = 0; j < 4; j++)
#pragma unroll
            for (int q = 0; q < 4; q++) acc[mt][j][q] = 0.0f;

    issue(s, 0);     CP_COMMIT();
    issue(s + 1, 1); CP_COMMIT();

    float* Tsm = (float*)(smem + SM_T1);
    int pb = 0;                      // stage of chunk g

    for (int g = s; g < e; g++) {
        CP_WAIT1();
        __syncthreads();

        const uint32_t Ab = sb + SM_A + (uint32_t)pb * 32768u;
        const uint32_t Bb = sb + SM_B + (uint32_t)pb * 16384u;
#pragma unroll
        for (int q = 0; q < 4; q++) {
            uint32_t afr[2][4];
#pragma unroll
            for (int mt = 0; mt < 2; mt++) {
#pragma unroll
                for (int half = 0; half < 2; half++) {
#pragma unroll
                    for (int dr = 0; dr < 2; dr++) {
                        float2 v;
                        uint32_t ad = Ab + aswz(wm * 32 + mt * 16 + lrow + dr * 8,
                                                q * 2 + half) + lq * 8;
                        asm volatile("ld.shared.v2.f32 {%0,%1}, [%2];"
                                     : "=f"(v.x), "=f"(v.y) : "r"(ad));
                        afr[mt][half * 2 + dr] = pack_bf16(v.x, v.y);
                    }
                }
            }
            uint32_t bfr[4][2];
#pragma unroll
            for (int j = 0; j < 4; j++) {
                int n = wn * 32 + j * 8 + lrow;
#pragma unroll
                for (int half = 0; half < 2; half++) {
                    asm volatile("ld.shared.b32 %0, [%1];"
                        : "=r"(bfr[j][half]) : "r"(Bb + bswz(n, q * 2 + half) + lq * 4));
                }
            }
#pragma unroll
            for (int mt = 0; mt < 2; mt++)
#pragma unroll
                for (int j = 0; j < 4; j++)
                    mma_bf16(acc[mt][j], afr[mt], bfr[j]);
        }

        // issue chunk g+2 into stage (pb+2)%3 == buffer consumed at g-1 (safe:
        // all its readers passed this iteration's __syncthreads).
        if (g + 2 < e) {
            int pn = pb + 2; if (pn >= 3) pn -= 3;
            issue(g + 2, pn);
        }
        CP_COMMIT();

        // ---- tile boundary or range end: flush partial R ----
        if ((g + 1 == e) || ((g + 1) % NCHUNK == 0)) {
            int m = g / NCHUNK;
            __syncthreads();
#pragma unroll
            for (int mt = 0; mt < 2; mt++) {
#pragma unroll
                for (int j = 0; j < 4; j++) {
                    int r0  = wm * 32 + mt * 16 + lrow;
                    int col = wn * 32 + j * 8 + lq * 2;
                    uint32_t a0 = sb + SM_T1 + (uint32_t)((r0 * T1_STRIDE + col) * 4);
                    uint32_t a1 = sb + SM_T1 + (uint32_t)(((r0 + 8) * T1_STRIDE + col) * 4);
                    asm volatile("st.shared.v2.f32 [%0], {%1,%2};"
                                 :: "r"(a0), "f"(acc[mt][j][0]), "f"(acc[mt][j][1]));
                    asm volatile("st.shared.v2.f32 [%0], {%1,%2};"
                                 :: "r"(a1), "f"(acc[mt][j][2]), "f"(acc[mt][j][3]));
                }
            }
            __syncthreads();
            if (tid < 256) {
                int fl = tid >> 7;
                int n  = tid & 127;
                float sum = 0.0f;
#pragma unroll 16
                for (int c2 = 0; c2 < 64; c2++)
                    sum += Tsm[(fl * 64 + c2) * T1_STRIDE + n] * __ldg(&wc[c2 * N_ + n]);
                int ord = (s > m * NCHUNK) ? 1 : 0;
                g_Rpart[m * 512 + ord * 256 + fl * 128 + n] = sum;
            }
#pragma unroll
            for (int mt = 0; mt < 2; mt++)
#pragma unroll
                for (int j = 0; j < 4; j++)
#pragma unroll
                    for (int q = 0; q < 4; q++) acc[mt][j][q] = 0.0f;
        }

        if (++pb >= 3) pb = 0;
    }
}

// ---------------------------------------------------------------------------
// 3) temporal conv: one warp per (b, n) row
// ---------------------------------------------------------------------------
__global__ void conv_kernel(const float* __restrict__ wt, const float* __restrict__ wb,
                            float* __restrict__ out) {
    __shared__ float rr[8][80];
    __shared__ float wts[8][10];
    int wid = threadIdx.x >> 5, lane = threadIdx.x & 31;
    int row = blockIdx.x * 8 + wid;        // row = b*N + n
    int b = row >> 7, n = row & 127;
    if (lane < 10) wts[wid][lane] = wt[lane * N_ + n];
#pragma unroll
    for (int t0 = lane; t0 < T_; t0 += 32) {
        int f = b * T_ + t0;
        int m = f >> 1, fl = f & 1;
        rr[wid][t0] = g_Rpart[m * 512 + fl * 128 + n]
                    + g_Rpart[m * 512 + 256 + fl * 128 + n];
    }
    __syncwarp();
    float bias = wb[n];
    for (int t0 = lane; t0 < TOUT_; t0 += 32) {
        float sum = bias;
#pragma unroll
        for (int k = 0; k < NT_; k++) sum += rr[wid][t0 + k] * wts[wid][k];
        out[(size_t)row * TOUT_ + t0] = sum;
    }
}

// ---------------------------------------------------------------------------
extern "C" void kernel_launch(void* const* d_in, const int* in_sizes, int n_in,
                              void* d_out, int out_size) {
    (void)in_sizes; (void)n_in; (void)out_size;
    const float* x   = (const float*)d_in[0];
    const float* wc  = (const float*)d_in[2];
    const float* wx  = (const float*)d_in[3];
    const float* wy  = (const float*)d_in[4];
    const float* wsx = (const float*)d_in[5];
    const float* wsy = (const float*)d_in[6];
    const float* wt  = (const float*)d_in[7];
    const float* wb  = (const float*)d_in[8];
    float* out = (float*)d_out;

    cudaFuncSetAttribute(gemm_kernel, cudaFuncAttributeMaxDynamicSharedMemorySize, SMEM_SZ);

    prep_kernel<<<160, 256>>>(wx, wy, wsx, wsy);
    gemm_kernel<<<GRID_G, 512, SMEM_SZ>>>(x, wc);
    conv_kernel<<<(B_ * N_) / 8, 256>>>(wt, wb, out);
}